// round 1
// baseline (speedup 1.0000x reference)
#include <cuda_runtime.h>
#include <cuda_bf16.h>
#include <math.h>

// Problem constants
#define BS   128
#define NE   32
#define NA   8
#define TE   8
#define TA   4
#define WD   300
#define HD   1024
#define G3   900          // 3*WD
#define NG   (BS*NE)      // 4096 graphs / entities
#define NATT (NG*NA)      // 32768 attribute phrases
#define NNODE 9           // 1 entity + 8 attributes

// ---------------- scratch (device globals; persist across replays) ----------
__device__ float g_xp_ent [NG   * TE * G3];   // [4096*8, 900]
__device__ float g_xp_attr[NATT * TA * G3];   // [32768*4, 900]
__device__ float g_gh     [NATT * G3];        // [32768, 900] reused
__device__ float g_h_ent  [NG   * WD];
__device__ float g_h_attr [NATT * WD];
__device__ float g_nodes  [NG * NNODE * HD];  // [4096, 9, 1024]
__device__ float g_hh     [NG * NNODE * HD];  // nodes @ Wg^T

// ---------------- generic tiled SGEMM: C = act(A(gather) @ W^T + bias) ------
// A: [M,K] dense, or gathered rows emb[gather[m]] when gather != nullptr
// W: [N,K] row-major.  outMap: 0 = contiguous [M,N];
//   1 = entity->nodes  (row m -> g_nodes + m*9*1024)
//   2 = attr  ->nodes  (row m -> g_nodes + ((m/8)*9 + 1 + m%8)*1024)
#define BM 64
#define BN 64
#define BK 16

__global__ void sgemm_kernel(const float* __restrict__ A,
                             const int*   __restrict__ gather,
                             const float* __restrict__ W,
                             const float* __restrict__ bias,
                             float* __restrict__ C,
                             int M, int N, int K,
                             int act, int outMap)
{
    __shared__ float As[BM][BK + 1];
    __shared__ float Bs[BN][BK + 1];

    const int tx = threadIdx.x;          // 0..15
    const int ty = threadIdx.y;          // 0..15
    const int tid = ty * 16 + tx;
    const int m0 = blockIdx.x * BM;
    const int n0 = blockIdx.y * BN;

    const int lk   = tid & 15;           // k within tile
    const int lrow = tid >> 4;           // row within pass (0..15)

    float acc[4][4];
#pragma unroll
    for (int i = 0; i < 4; ++i)
#pragma unroll
        for (int j = 0; j < 4; ++j) acc[i][j] = 0.f;

    for (int k0 = 0; k0 < K; k0 += BK) {
        // load A tile (coalesced along K), conflict-free STS
#pragma unroll
        for (int p = 0; p < 4; ++p) {
            int m = m0 + lrow + p * 16;
            int k = k0 + lk;
            float v = 0.f;
            if (m < M && k < K) {
                const float* arow = gather ? (A + (long)gather[m] * K)
                                           : (A + (long)m * K);
                v = arow[k];
            }
            As[lrow + p * 16][lk] = v;
        }
        // load W tile
#pragma unroll
        for (int p = 0; p < 4; ++p) {
            int n = n0 + lrow + p * 16;
            int k = k0 + lk;
            float v = 0.f;
            if (n < N && k < K) v = W[(long)n * K + k];
            Bs[lrow + p * 16][lk] = v;
        }
        __syncthreads();

#pragma unroll
        for (int kk = 0; kk < BK; ++kk) {
            float a0 = As[ty * 4 + 0][kk];
            float a1 = As[ty * 4 + 1][kk];
            float a2 = As[ty * 4 + 2][kk];
            float a3 = As[ty * 4 + 3][kk];
            float b0 = Bs[tx * 4 + 0][kk];
            float b1 = Bs[tx * 4 + 1][kk];
            float b2 = Bs[tx * 4 + 2][kk];
            float b3 = Bs[tx * 4 + 3][kk];
            acc[0][0] += a0 * b0; acc[0][1] += a0 * b1; acc[0][2] += a0 * b2; acc[0][3] += a0 * b3;
            acc[1][0] += a1 * b0; acc[1][1] += a1 * b1; acc[1][2] += a1 * b2; acc[1][3] += a1 * b3;
            acc[2][0] += a2 * b0; acc[2][1] += a2 * b1; acc[2][2] += a2 * b2; acc[2][3] += a2 * b3;
            acc[3][0] += a3 * b0; acc[3][1] += a3 * b1; acc[3][2] += a3 * b2; acc[3][3] += a3 * b3;
        }
        __syncthreads();
    }

#pragma unroll
    for (int i = 0; i < 4; ++i) {
        int m = m0 + ty * 4 + i;
        if (m >= M) continue;
        long base;
        if (outMap == 0)      base = (long)m * N;
        else if (outMap == 1) base = (long)m * NNODE * HD;
        else                  base = ((long)(m >> 3) * NNODE + 1 + (m & 7)) * HD;
#pragma unroll
        for (int j = 0; j < 4; ++j) {
            int n = n0 + tx * 4 + j;
            if (n >= N) continue;
            float v = acc[i][j];
            if (bias) v += bias[n];
            if (act)  v = fmaxf(v, 0.f);
            C[base + n] = v;
        }
    }
}

// ---------------- GRU gate update --------------------------------------
// xp: [nrows, T, 900] precomputed; gh: [nrows, 900]; h: [nrows, 300]
__global__ void gru_gate_kernel(const float* __restrict__ xp,
                                const float* __restrict__ gh,
                                float* __restrict__ h,
                                const int* __restrict__ len,
                                int t, int T, int nrows)
{
    int idx = blockIdx.x * blockDim.x + threadIdx.x;
    if (idx >= nrows * WD) return;
    int i = idx / WD;
    int d = idx - i * WD;
    if (t >= len[i]) return;                 // state frozen past length
    const float* x = xp + ((long)i * T + t) * G3;
    const float* g = gh + (long)i * G3;
    float r = 1.f / (1.f + expf(-(x[d]          + g[d])));
    float z = 1.f / (1.f + expf(-(x[WD + d]     + g[WD + d])));
    float n = tanhf(x[2 * WD + d] + r * g[2 * WD + d]);
    float hp = h[idx];
    h[idx] = (1.f - z) * n + z * hp;
}

// ---------------- GAT (node-0 row only) ---------------------------------
// hh: [G, 9, 1024].  Only out[:,0,:] is needed by the reference.
__global__ void gat_kernel(const float* __restrict__ hh,
                           const float* __restrict__ a_src,
                           const float* __restrict__ a_dst,
                           const unsigned char* __restrict__ amask, // [G,8,4] bool
                           float* __restrict__ out)
{
    int g = blockIdx.x;
    const float* base = hh + (long)g * NNODE * HD;
    __shared__ float sdots[10];
    __shared__ float salpha[NNODE];

    int tid  = threadIdx.x;
    int warp = tid >> 5, lane = tid & 31;

    float partial = 0.f;
    if (warp < 9) {                       // ed[j]
        const float* row = base + warp * HD;
        for (int d = lane; d < HD; d += 32) partial += row[d] * a_dst[d];
    } else {                              // es[0]
        for (int d = lane; d < HD; d += 32) partial += base[d] * a_src[d];
    }
#pragma unroll
    for (int off = 16; off; off >>= 1)
        partial += __shfl_down_sync(0xffffffffu, partial, off);
    if (lane == 0) sdots[warp] = partial;
    __syncthreads();

    if (tid == 0) {
        float es0 = sdots[9];
        float e[NNODE];
#pragma unroll
        for (int j = 0; j < NNODE; ++j) {
            bool valid;
            if (j == 0) valid = true;
            else {
                const unsigned char* m = amask + ((long)g * NA + (j - 1)) * TA;
                valid = !(m[0] && m[1] && m[2] && m[3]);   // any unmasked token
            }
            if (valid) {
                float v = es0 + sdots[j];
                e[j] = v > 0.f ? v : 0.2f * v;             // leaky_relu 0.2
            } else {
                e[j] = -1e9f;
            }
        }
        float mx = e[0];
#pragma unroll
        for (int j = 1; j < NNODE; ++j) mx = fmaxf(mx, e[j]);
        float s = 0.f, ex[NNODE];
#pragma unroll
        for (int j = 0; j < NNODE; ++j) { ex[j] = expf(e[j] - mx); s += ex[j]; }
        float inv = 1.f / s;
#pragma unroll
        for (int j = 0; j < NNODE; ++j) salpha[j] = ex[j] * inv;
    }
    __syncthreads();

    for (int d = tid; d < HD; d += blockDim.x) {
        float s = 0.f;
#pragma unroll
        for (int j = 0; j < NNODE; ++j) s += salpha[j] * base[j * HD + d];
        out[(long)g * HD + d] = s > 0.f ? s : (expf(s) - 1.f);   // elu
    }
}

// ---------------- launch ---------------------------------------------------
extern "C" void kernel_launch(void* const* d_in, const int* in_sizes, int n_in,
                              void* d_out, int out_size)
{
    const int*   ent_tok  = (const int*)  d_in[0];
    const int*   ent_len  = (const int*)  d_in[1];
    // d_in[2]: entity_padding_mask (unused by reference)
    const int*   at_tok   = (const int*)  d_in[3];
    const int*   at_len   = (const int*)  d_in[4];
    const unsigned char* at_mask = (const unsigned char*)d_in[5];
    const float* emb      = (const float*)d_in[6];
    const float* Wih_ent  = (const float*)d_in[7];
    const float* Whh_ent  = (const float*)d_in[8];
    const float* bih_ent  = (const float*)d_in[9];
    const float* bhh_ent  = (const float*)d_in[10];
    const float* Wih_attr = (const float*)d_in[11];
    const float* Whh_attr = (const float*)d_in[12];
    const float* bih_attr = (const float*)d_in[13];
    const float* bhh_attr = (const float*)d_in[14];
    const float* Wfc      = (const float*)d_in[15];
    const float* bfc      = (const float*)d_in[16];
    const float* Wg       = (const float*)d_in[17];
    const float* a_src    = (const float*)d_in[18];
    const float* a_dst    = (const float*)d_in[19];
    float* out = (float*)d_out;

    float *xp_ent, *xp_attr, *gh, *h_ent, *h_attr, *nodes, *hh;
    cudaGetSymbolAddress((void**)&xp_ent,  g_xp_ent);
    cudaGetSymbolAddress((void**)&xp_attr, g_xp_attr);
    cudaGetSymbolAddress((void**)&gh,      g_gh);
    cudaGetSymbolAddress((void**)&h_ent,   g_h_ent);
    cudaGetSymbolAddress((void**)&h_attr,  g_h_attr);
    cudaGetSymbolAddress((void**)&nodes,   g_nodes);
    cudaGetSymbolAddress((void**)&hh,      g_hh);

    // h0 = 0 (must re-zero every replay)
    cudaMemsetAsync(h_ent,  0, (size_t)NG   * WD * sizeof(float));
    cudaMemsetAsync(h_attr, 0, (size_t)NATT * WD * sizeof(float));

    dim3 blk(16, 16);
    const int colT900  = (G3 + BN - 1) / BN;   // 15
    const int colT1024 = HD / BN;              // 16

    // xp = emb[tokens] @ Wih^T + bih  (one big GEMM each)
    {
        int M = NG * TE;   // 32768
        sgemm_kernel<<<dim3((M + BM - 1) / BM, colT900), blk>>>(
            emb, ent_tok, Wih_ent, bih_ent, xp_ent, M, G3, WD, 0, 0);
    }
    {
        int M = NATT * TA; // 131072
        sgemm_kernel<<<dim3((M + BM - 1) / BM, colT900), blk>>>(
            emb, at_tok, Wih_attr, bih_attr, xp_attr, M, G3, WD, 0, 0);
    }

    // entity GRU: 8 sequential steps
    for (int t = 0; t < TE; ++t) {
        sgemm_kernel<<<dim3(NG / BM, colT900), blk>>>(
            h_ent, nullptr, Whh_ent, bhh_ent, gh, NG, G3, WD, 0, 0);
        int nthr = NG * WD;
        gru_gate_kernel<<<(nthr + 255) / 256, 256>>>(
            xp_ent, gh, h_ent, ent_len, t, TE, NG);
    }

    // attribute GRU: 4 sequential steps
    for (int t = 0; t < TA; ++t) {
        sgemm_kernel<<<dim3(NATT / BM, colT900), blk>>>(
            h_attr, nullptr, Whh_attr, bhh_attr, gh, NATT, G3, WD, 0, 0);
        int nthr = NATT * WD;
        gru_gate_kernel<<<(nthr + 255) / 256, 256>>>(
            xp_attr, gh, h_attr, at_len, t, TA, NATT);
    }

    // FC + ReLU, writing directly into node layout [G, 9, HD]
    sgemm_kernel<<<dim3(NG / BM,   colT1024), blk>>>(
        h_ent,  nullptr, Wfc, bfc, nodes, NG,   HD, WD, 1, 1);
    sgemm_kernel<<<dim3(NATT / BM, colT1024), blk>>>(
        h_attr, nullptr, Wfc, bfc, nodes, NATT, HD, WD, 1, 2);

    // GAT projection: hh = nodes @ Wg^T
    sgemm_kernel<<<dim3((NG * NNODE) / BM, colT1024), blk>>>(
        nodes, nullptr, Wg, nullptr, hh, NG * NNODE, HD, HD, 0, 0);

    // attention (row 0 only) + elu -> output
    gat_kernel<<<NG, 320>>>(hh, a_src, a_dst, at_mask, out);
}

// round 2
// speedup vs baseline: 1.6670x; 1.6670x over previous
#include <cuda_runtime.h>
#include <cuda_bf16.h>
#include <math.h>

// Problem constants
#define BS   128
#define NE   32
#define NA   8
#define TE   8
#define TA   4
#define WD   300
#define HD   1024
#define G3   900          // 3*WD
#define NG   (BS*NE)      // 4096 graphs / entities
#define NATT (NG*NA)      // 32768 attribute phrases
#define NNODE 9           // 1 entity + 8 attributes

// ---------------- scratch (device globals; persist across replays) ----------
__device__ float g_xp_ent [NG   * TE * G3];
__device__ float g_xp_attr[NATT * TA * G3];
__device__ float g_gh     [NATT * G3];        // gh scratch; later reused for mix
__device__ float g_h_ent  [NG   * WD];
__device__ float g_h_attr [NATT * WD];
__device__ float g_nodes  [NG * NNODE * HD];  // [4096, 9, 1024]
__device__ float g_va     [HD];               // Wg^T a_src
__device__ float g_vb     [HD];               // Wg^T a_dst

// ---------------- SGEMM: C = act(A(gather) @ W^T + bias) -------------------
// 128x128 tile, BK=8, 256 threads, 8x8 microtile, double-buffered smem.
#define BM 128
#define BN 128
#define BK 8
#define SMS 132   // padded smem row stride (floats)

__global__ __launch_bounds__(256, 2)
void sgemm128(const float* __restrict__ A, const int* __restrict__ gather,
              const float* __restrict__ W, const float* __restrict__ bias,
              float* __restrict__ C, int M, int N, int K, int act, int outMap)
{
    __shared__ float As[2][BK][SMS];
    __shared__ float Bs[2][BK][SMS];

    const int tid   = threadIdx.x;
    const int m0    = blockIdx.x * BM;
    const int n0    = blockIdx.y * BN;
    const int ldRow = tid >> 1;          // 0..127
    const int ldK   = (tid & 1) * 4;     // 0 or 4
    const int rb    = (tid >> 4) * 8;    // micro-tile row base (0..120)
    const int cb    = (tid & 15) * 8;    // micro-tile col base

    const float* Aptr = nullptr;
    {
        int m = m0 + ldRow;
        if (m < M) Aptr = gather ? A + (long)gather[m] * K : A + (long)m * K;
    }
    const float* Wptr = (n0 + ldRow < N) ? W + (long)(n0 + ldRow) * K : nullptr;

    float acc[8][8];
#pragma unroll
    for (int i = 0; i < 8; ++i)
#pragma unroll
        for (int j = 0; j < 8; ++j) acc[i][j] = 0.f;

    const int nk = (K + BK - 1) / BK;
    const float4 z4 = make_float4(0.f, 0.f, 0.f, 0.f);
    float4 aR, bR;

    // prefetch tile 0 (K%4==0 guaranteed -> float4 fully in/out of bounds)
    {
        int k = ldK;
        aR = (Aptr && k < K) ? *(const float4*)(Aptr + k) : z4;
        bR = (Wptr && k < K) ? *(const float4*)(Wptr + k) : z4;
    }
    As[0][ldK + 0][ldRow] = aR.x; As[0][ldK + 1][ldRow] = aR.y;
    As[0][ldK + 2][ldRow] = aR.z; As[0][ldK + 3][ldRow] = aR.w;
    Bs[0][ldK + 0][ldRow] = bR.x; Bs[0][ldK + 1][ldRow] = bR.y;
    Bs[0][ldK + 2][ldRow] = bR.z; Bs[0][ldK + 3][ldRow] = bR.w;
    __syncthreads();

    for (int t = 0; t < nk; ++t) {
        const int buf = t & 1;
        if (t + 1 < nk) {
            int k = (t + 1) * BK + ldK;
            aR = (Aptr && k < K) ? *(const float4*)(Aptr + k) : z4;
            bR = (Wptr && k < K) ? *(const float4*)(Wptr + k) : z4;
        }
#pragma unroll
        for (int kk = 0; kk < BK; ++kk) {
            float a[8], b[8];
            *(float4*)&a[0] = *(const float4*)&As[buf][kk][rb];
            *(float4*)&a[4] = *(const float4*)&As[buf][kk][rb + 4];
            *(float4*)&b[0] = *(const float4*)&Bs[buf][kk][cb];
            *(float4*)&b[4] = *(const float4*)&Bs[buf][kk][cb + 4];
#pragma unroll
            for (int i = 0; i < 8; ++i)
#pragma unroll
                for (int j = 0; j < 8; ++j)
                    acc[i][j] += a[i] * b[j];
        }
        if (t + 1 < nk) {
            const int nb = buf ^ 1;
            As[nb][ldK + 0][ldRow] = aR.x; As[nb][ldK + 1][ldRow] = aR.y;
            As[nb][ldK + 2][ldRow] = aR.z; As[nb][ldK + 3][ldRow] = aR.w;
            Bs[nb][ldK + 0][ldRow] = bR.x; Bs[nb][ldK + 1][ldRow] = bR.y;
            Bs[nb][ldK + 2][ldRow] = bR.z; Bs[nb][ldK + 3][ldRow] = bR.w;
        }
        __syncthreads();
    }

    // epilogue (vectorized float4 stores; N%4==0 for all call sites)
#pragma unroll
    for (int i = 0; i < 8; ++i) {
        int m = m0 + rb + i;
        if (m >= M) continue;
        long base;
        if (outMap == 0)      base = (long)m * N;
        else if (outMap == 1) base = (long)m * NNODE * HD;
        else                  base = ((long)(m >> 3) * NNODE + 1 + (m & 7)) * (long)HD;
#pragma unroll
        for (int j0 = 0; j0 < 8; j0 += 4) {
            int n = n0 + cb + j0;
            if (n >= N) continue;
            float4 v;
            float* vp = &v.x;
#pragma unroll
            for (int j = 0; j < 4; ++j) {
                float x = acc[i][j0 + j];
                if (bias) x += bias[n + j];
                if (act == 1)      x = fmaxf(x, 0.f);
                else if (act == 2) x = x > 0.f ? x : expm1f(x);
                vp[j] = x;
            }
            *(float4*)(C + base + n) = v;
        }
    }
}

// ---------------- GRU gate update -------------------------------------------
__global__ void gru_gate_kernel(const float* __restrict__ xp,
                                const float* __restrict__ gh,
                                float* __restrict__ h,
                                const int* __restrict__ len,
                                int t, int T, int nrows)
{
    int idx = blockIdx.x * blockDim.x + threadIdx.x;
    if (idx >= nrows * WD) return;
    int i = idx / WD;
    int d = idx - i * WD;
    if (t >= len[i]) return;
    const float* x = xp + ((long)i * T + t) * G3;
    const float* g = gh + (long)i * G3;
    float r = 1.f / (1.f + expf(-(x[d]          + g[d])));
    float z = 1.f / (1.f + expf(-(x[WD + d]     + g[WD + d])));
    float n = tanhf(x[2 * WD + d] + r * g[2 * WD + d]);
    float hp = h[idx];
    h[idx] = (1.f - z) * n + z * hp;
}

// ---------------- va/vb = Wg^T a_src / Wg^T a_dst ---------------------------
__global__ void wgt_vec_kernel(const float* __restrict__ Wg,
                               const float* __restrict__ a_src,
                               const float* __restrict__ a_dst,
                               float* __restrict__ va, float* __restrict__ vb)
{
    int k = blockIdx.x * blockDim.x + threadIdx.x;
    if (k >= HD) return;
    float sa = 0.f, sb = 0.f;
    for (int d = 0; d < HD; ++d) {
        float w = Wg[(long)d * HD + k];
        sa += w * a_src[d];
        sb += w * a_dst[d];
    }
    va[k] = sa;
    vb[k] = sb;
}

// ---------------- GAT dots + softmax + node mix ------------------------------
// es0 = nodes0.va, ed[j] = nodes_j.vb; alpha over 9 nodes; mix = sum alpha_j nodes_j
__global__ void gat_mix_kernel(const float* __restrict__ nodes,
                               const float* __restrict__ va,
                               const float* __restrict__ vb,
                               const unsigned char* __restrict__ amask, // [G,8,4]
                               float* __restrict__ mix)
{
    int g = blockIdx.x;
    const float* base = nodes + (long)g * NNODE * HD;
    __shared__ float sdots[10];
    __shared__ float salpha[NNODE];

    int tid  = threadIdx.x;
    int warp = tid >> 5, lane = tid & 31;

    float partial = 0.f;
    if (warp < 9) {                       // ed[j]
        const float* row = base + warp * HD;
        for (int d = lane; d < HD; d += 32) partial += row[d] * vb[d];
    } else {                              // es0
        for (int d = lane; d < HD; d += 32) partial += base[d] * va[d];
    }
#pragma unroll
    for (int off = 16; off; off >>= 1)
        partial += __shfl_down_sync(0xffffffffu, partial, off);
    if (lane == 0) sdots[warp] = partial;
    __syncthreads();

    if (tid == 0) {
        float es0 = sdots[9];
        float e[NNODE];
#pragma unroll
        for (int j = 0; j < NNODE; ++j) {
            bool valid;
            if (j == 0) valid = true;
            else {
                const unsigned char* m = amask + ((long)g * NA + (j - 1)) * TA;
                valid = !(m[0] && m[1] && m[2] && m[3]);
            }
            if (valid) {
                float v = es0 + sdots[j];
                e[j] = v > 0.f ? v : 0.2f * v;
            } else {
                e[j] = -1e9f;
            }
        }
        float mx = e[0];
#pragma unroll
        for (int j = 1; j < NNODE; ++j) mx = fmaxf(mx, e[j]);
        float s = 0.f, ex[NNODE];
#pragma unroll
        for (int j = 0; j < NNODE; ++j) { ex[j] = expf(e[j] - mx); s += ex[j]; }
        float inv = 1.f / s;
#pragma unroll
        for (int j = 0; j < NNODE; ++j) salpha[j] = ex[j] * inv;
    }
    __syncthreads();

    for (int d = tid; d < HD; d += blockDim.x) {
        float s = 0.f;
#pragma unroll
        for (int j = 0; j < NNODE; ++j) s += salpha[j] * base[j * HD + d];
        mix[(long)g * HD + d] = s;
    }
}

// ---------------- launch -----------------------------------------------------
extern "C" void kernel_launch(void* const* d_in, const int* in_sizes, int n_in,
                              void* d_out, int out_size)
{
    const int*   ent_tok  = (const int*)  d_in[0];
    const int*   ent_len  = (const int*)  d_in[1];
    const int*   at_tok   = (const int*)  d_in[3];
    const int*   at_len   = (const int*)  d_in[4];
    const unsigned char* at_mask = (const unsigned char*)d_in[5];
    const float* emb      = (const float*)d_in[6];
    const float* Wih_ent  = (const float*)d_in[7];
    const float* Whh_ent  = (const float*)d_in[8];
    const float* bih_ent  = (const float*)d_in[9];
    const float* bhh_ent  = (const float*)d_in[10];
    const float* Wih_attr = (const float*)d_in[11];
    const float* Whh_attr = (const float*)d_in[12];
    const float* bih_attr = (const float*)d_in[13];
    const float* bhh_attr = (const float*)d_in[14];
    const float* Wfc      = (const float*)d_in[15];
    const float* bfc      = (const float*)d_in[16];
    const float* Wg       = (const float*)d_in[17];
    const float* a_src    = (const float*)d_in[18];
    const float* a_dst    = (const float*)d_in[19];
    float* out = (float*)d_out;

    float *xp_ent, *xp_attr, *gh, *h_ent, *h_attr, *nodes, *va, *vb;
    cudaGetSymbolAddress((void**)&xp_ent,  g_xp_ent);
    cudaGetSymbolAddress((void**)&xp_attr, g_xp_attr);
    cudaGetSymbolAddress((void**)&gh,      g_gh);
    cudaGetSymbolAddress((void**)&h_ent,   g_h_ent);
    cudaGetSymbolAddress((void**)&h_attr,  g_h_attr);
    cudaGetSymbolAddress((void**)&nodes,   g_nodes);
    cudaGetSymbolAddress((void**)&va,      g_va);
    cudaGetSymbolAddress((void**)&vb,      g_vb);
    float* mixbuf = gh;   // reuse gh scratch after GRU phase

    cudaMemsetAsync(h_ent,  0, (size_t)NG   * WD * sizeof(float));
    cudaMemsetAsync(h_attr, 0, (size_t)NATT * WD * sizeof(float));

    const int cB900  = (G3 + BN - 1) / BN;   // 8
    const int cB1024 = HD / BN;              // 8

    // xp = emb[tokens] @ Wih^T + bih
    sgemm128<<<dim3((NG * TE) / BM, cB900), 256>>>(
        emb, ent_tok, Wih_ent, bih_ent, xp_ent, NG * TE, G3, WD, 0, 0);
    sgemm128<<<dim3((NATT * TA) / BM, cB900), 256>>>(
        emb, at_tok, Wih_attr, bih_attr, xp_attr, NATT * TA, G3, WD, 0, 0);

    // va/vb for GAT (independent; launch early)
    wgt_vec_kernel<<<(HD + 255) / 256, 256>>>(Wg, a_src, a_dst, va, vb);

    // entity GRU
    for (int t = 0; t < TE; ++t) {
        sgemm128<<<dim3(NG / BM, cB900), 256>>>(
            h_ent, nullptr, Whh_ent, bhh_ent, gh, NG, G3, WD, 0, 0);
        gru_gate_kernel<<<(NG * WD + 255) / 256, 256>>>(
            xp_ent, gh, h_ent, ent_len, t, TE, NG);
    }

    // attribute GRU
    for (int t = 0; t < TA; ++t) {
        sgemm128<<<dim3(NATT / BM, cB900), 256>>>(
            h_attr, nullptr, Whh_attr, bhh_attr, gh, NATT, G3, WD, 0, 0);
        gru_gate_kernel<<<(NATT * WD + 255) / 256, 256>>>(
            xp_attr, gh, h_attr, at_len, t, TA, NATT);
    }

    // FC + ReLU -> node layout [G, 9, HD]
    sgemm128<<<dim3(NG / BM,   cB1024), 256>>>(
        h_ent,  nullptr, Wfc, bfc, nodes, NG,   HD, WD, 1, 1);
    sgemm128<<<dim3(NATT / BM, cB1024), 256>>>(
        h_attr, nullptr, Wfc, bfc, nodes, NATT, HD, WD, 1, 2);

    // GAT: dots + alpha + mix (no big Wg GEMM needed)
    gat_mix_kernel<<<NG, 320>>>(nodes, va, vb, at_mask, mixbuf);

    // out = elu(mix @ Wg^T)
    sgemm128<<<dim3(NG / BM, cB1024), 256>>>(
        mixbuf, nullptr, Wg, nullptr, out, NG, HD, HD, 2, 0);
}